// round 12
// baseline (speedup 1.0000x reference)
#include <cuda_runtime.h>
#include <math.h>

#define NB 4
#define CIN 256
#define COUT 128
#define HH 64
#define WW 64
#define HO 128
#define WO 128
#define KK9 9
#define CK (CIN*KK9)   // 2304

#define PADV 68        // sV row stride (floats)
#define PADW 132       // sW row stride (floats)

// ---- scratch (device globals; no allocation) ----
__device__ float g_xn[NB*HH*WW*CIN];        // x in NHWC, 16 MB
__device__ float g_om[NB*27*HH*WW];         // offset conv output, NCHW
__device__ float g_wT[CK*COUT];             // dcn weights (ck=k*256+c, o)
__device__ float g_wTo[CK*32];              // offconv weights (c*9+k, co) padded 27->32
__device__ float g_wT2[16*COUT*COUT];       // deconv weights (tap, i, o)
__device__ float g_y1[NB*HH*WW*COUT];       // dcn partial half0 -> final y1 (post-combine)
__device__ float g_y1b[NB*HH*WW*COUT];      // dcn partial half1
__device__ float g_z[NB*HO*WO*COUT];        // deconv output NHWC (pre-BN)
__device__ float g_part1[256*2*COUT];
__device__ float g_part2[512*2*COUT];
__device__ float g_scale1[COUT], g_shift1[COUT];
__device__ float g_scale2[COUT], g_shift2[COUT];

// ---- packed fp32x2 helpers (sm_103a FFMA2) ----
__device__ __forceinline__ unsigned long long pack2(float v) {
    unsigned long long r;
    asm("mov.b64 %0, {%1, %1};" : "=l"(r) : "f"(v));
    return r;
}
__device__ __forceinline__ void fma2(unsigned long long& a, unsigned long long v, unsigned long long w) {
    asm("fma.rn.f32x2 %0, %1, %2, %0;" : "+l"(a) : "l"(v), "l"(w));
}
__device__ __forceinline__ float2 unpack2(unsigned long long a) {
    float2 f;
    asm("mov.b64 {%0, %1}, %2;" : "=f"(f.x), "=f"(f.y) : "l"(a));
    return f;
}

// shared 64ck x (64pix x 128o) tile-multiply: 4 o x 8 pix per thread
__device__ __forceinline__ void mm_tile(const float* sV, const float* sW,
                                        int og, int pg,
                                        unsigned long long acc[4][4]) {
    #pragma unroll 4
    for (int ck = 0; ck < 64; ck++) {
        const float* vrow = sV + ck*PADV + pg*8;
        ulonglong2 va = *(const ulonglong2*)(vrow);
        ulonglong2 vb = *(const ulonglong2*)(vrow + 4);
        float4 wq = *(const float4*)(sW + ck*PADW + og*4);
        unsigned long long w0 = pack2(wq.x), w1 = pack2(wq.y);
        unsigned long long w2 = pack2(wq.z), w3 = pack2(wq.w);
        fma2(acc[0][0], va.x, w0); fma2(acc[0][1], va.y, w0);
        fma2(acc[0][2], vb.x, w0); fma2(acc[0][3], vb.y, w0);
        fma2(acc[1][0], va.x, w1); fma2(acc[1][1], va.y, w1);
        fma2(acc[1][2], vb.x, w1); fma2(acc[1][3], vb.y, w1);
        fma2(acc[2][0], va.x, w2); fma2(acc[2][1], va.y, w2);
        fma2(acc[2][2], vb.x, w2); fma2(acc[2][3], vb.y, w2);
        fma2(acc[3][0], va.x, w3); fma2(acc[3][1], va.y, w3);
        fma2(acc[3][2], vb.x, w3); fma2(acc[3][3], vb.y, w3);
    }
}

// ---- 0. merged weight reorders ----
__global__ void k_prep_w(const float* __restrict__ w_dcn,
                         const float* __restrict__ w_off,
                         const float* __restrict__ w_up) {
    int idx = blockIdx.x * blockDim.x + threadIdx.x;
    if (idx < CK*COUT) {              // dcn: wT[(k*256+c)*128 + o] = w_dcn[o][c][k]
        int o = idx & 127;
        int ck = idx >> 7;
        int k = ck >> 8;
        int c = ck & 255;
        g_wT[idx] = w_dcn[o*CK + c*9 + k];
    }
    if (idx < CK*32) {                // offconv: wTo[(c*9+k)*32 + co]
        int co = idx & 31;
        int ck = idx >> 5;
        g_wTo[idx] = (co < 27) ? w_off[co*CK + ck] : 0.0f;
    }
    if (idx < 16*COUT*COUT) {         // deconv: wT2[tap][i][o]
        int tap = idx >> 14;
        int rem = idx & 16383;
        int i = rem >> 7;
        int o = rem & 127;
        g_wT2[idx] = w_up[(i*COUT + o)*16 + tap];
    }
}

// ---- 1. transpose x NCHW -> NHWC ----
__global__ void k_transpose_x(const float* __restrict__ x) {
    int idx = blockIdx.x * blockDim.x + threadIdx.x;
    if (idx >= NB*HH*WW*CIN) return;
    int c = idx & (CIN-1);
    int pix = idx >> 8;
    int b = pix >> 12;
    int h = (pix >> 6) & 63;
    int w = pix & 63;
    g_xn[idx] = x[((b*CIN + c)*HH + h)*WW + w];
}

// ---- 2. offset conv, shared-tile version ----
__global__ void k_offconv(const float* __restrict__ b_off) {
    __shared__ float tile[CIN*30];
    __shared__ float sred[32*8*8];

    int tid = threadIdx.x;
    int pixbase = blockIdx.x * 8;
    int b  = pixbase >> 12;
    int h  = (pixbase >> 6) & 63;
    int w0 = pixbase & 63;

    {
        int c = tid;
        const float* xb = g_xn + (size_t)b*HH*WW*CIN;
        #pragma unroll
        for (int r = 0; r < 3; r++) {
            int yy = h - 1 + r;
            bool vy = (yy >= 0 && yy < HH);
            #pragma unroll
            for (int col = 0; col < 10; col++) {
                int xx = w0 - 1 + col;
                float v = 0.f;
                if (vy && xx >= 0 && xx < WW) v = xb[(yy*WW + xx)*CIN + c];
                tile[c*30 + r*10 + col] = v;
            }
        }
    }
    __syncthreads();

    {
        int o = tid & 31;
        int slice = tid >> 5;
        float acc[8] = {0,0,0,0,0,0,0,0};
        for (int cl = 0; cl < 32; cl++) {
            int c = slice*32 + cl;
            const float* tc = tile + c*30;
            float t[30];
            #pragma unroll
            for (int j = 0; j < 30; j++) t[j] = tc[j];
            const float* wp = g_wTo + (size_t)(c*9)*32 + o;
            #pragma unroll
            for (int ky = 0; ky < 3; ky++) {
                #pragma unroll
                for (int kx = 0; kx < 3; kx++) {
                    float wv = wp[(ky*3 + kx)*32];
                    #pragma unroll
                    for (int p = 0; p < 8; p++)
                        acc[p] += t[ky*10 + kx + p] * wv;
                }
            }
        }
        #pragma unroll
        for (int p = 0; p < 8; p++)
            sred[(o*8 + slice)*8 + p] = acc[p];
    }
    __syncthreads();

    if (tid < 27*8) {
        int co = tid >> 3;
        int p  = tid & 7;
        float s = b_off[co];
        #pragma unroll
        for (int sl = 0; sl < 8; sl++)
            s += sred[(co*8 + sl)*8 + p];
        g_om[((b*27 + co)*HH + h)*WW + w0 + p] = s;
    }
}

// ---- 3. DCN as K-split, K-tiled GEMM with fused deformable gather ----
// grid 512: part = blk>>8 selects kt range [part*18, part*18+18); row = blk&255.
// Partials (no bias) -> g_y1 (part 0) / g_y1b (part 1); combine in k_bn1_part.
#define DCN_SW_F   (64*PADW)                 // 8448 floats
#define DCN_SV_F   (64*PADV)                 // 4352
#define DCN_WT_F   (9*64*4)                  // 2304
#define DCN_SMEM_B ((DCN_SW_F + DCN_SV_F + DCN_WT_F + DCN_WT_F) * 4)   // 69632 B

__global__ void k_dcn_gemm() {
    extern __shared__ float dsm[];
    float* sW   = dsm;
    float* sV   = dsm + DCN_SW_F;
    float* swtA = dsm + DCN_SW_F + DCN_SV_F;
    int*   soffA = (int*)(dsm + DCN_SW_F + DCN_SV_F + DCN_WT_F);

    int t = threadIdx.x;
    int part = blockIdx.x >> 8;       // 0 or 1
    int blk  = blockIdx.x & 255;
    int b = blk >> 6;
    int h = blk & 63;
    int pixbase = blk * 64;

    // meta: per (k, w): 4 corner weights + 4 clamped offsets
    for (int idx = t; idx < 576; idx += 256) {
        int k = idx >> 6, w = idx & 63;
        int ky = k / 3, kx = k % 3;
        const float* omb = g_om + (b*27)*4096 + h*64 + w;
        float dy = omb[(2*k)*4096];
        float dx = omb[(2*k + 1)*4096];
        float mm = omb[(18 + k)*4096];
        float mask = 1.0f / (1.0f + expf(-mm));
        float ys = (float)(h - 1 + ky) + dy;
        float xs = (float)(w - 1 + kx) + dx;
        float y0f = floorf(ys), x0f = floorf(xs);
        float ly = ys - y0f, lx = xs - x0f;
        int y0 = (int)y0f, x0 = (int)x0f;
        int y1i = y0 + 1, x1i = x0 + 1;
        float vy0 = (y0  >= 0 && y0  < 64) ? 1.0f : 0.0f;
        float vy1 = (y1i >= 0 && y1i < 64) ? 1.0f : 0.0f;
        float vx0 = (x0  >= 0 && x0  < 64) ? 1.0f : 0.0f;
        float vx1 = (x1i >= 0 && x1i < 64) ? 1.0f : 0.0f;
        swtA[idx*4+0] = (1.0f-ly)*(1.0f-lx)*mask*vy0*vx0;
        swtA[idx*4+1] = (1.0f-ly)*lx       *mask*vy0*vx1;
        swtA[idx*4+2] = ly       *(1.0f-lx)*mask*vy1*vx0;
        swtA[idx*4+3] = ly*lx              *mask*vy1*vx1;
        int y0c = min(max(y0, 0), 63),  y1c = min(max(y1i, 0), 63);
        int x0c = min(max(x0, 0), 63),  x1c = min(max(x1i, 0), 63);
        soffA[idx*4+0] = (y0c*64 + x0c)*CIN;
        soffA[idx*4+1] = (y0c*64 + x1c)*CIN;
        soffA[idx*4+2] = (y1c*64 + x0c)*CIN;
        soffA[idx*4+3] = (y1c*64 + x1c)*CIN;
    }
    __syncthreads();

    const float* xb = g_xn + (size_t)b*HH*WW*CIN;
    int og = t & 31, pg = t >> 5;
    unsigned long long acc[4][4] = {{0ull,0ull,0ull,0ull},{0ull,0ull,0ull,0ull},
                                    {0ull,0ull,0ull,0ull},{0ull,0ull,0ull,0ull}};

    int kt0 = part * 18;
    for (int kt = kt0; kt < kt0 + 18; kt++) {
        // stage W tile (64 ck x 128 o)
        #pragma unroll
        for (int i = 0; i < 8; i++) {
            int f4 = t + i*256;
            int ckl = f4 >> 5, of4 = f4 & 31;
            float4 wv = *(const float4*)(g_wT + (size_t)(kt*64 + ckl)*COUT + of4*4);
            *(float4*)(sW + ckl*PADW + of4*4) = wv;
        }
        // gather V tile (64 c x 64 pix), transposed to [ck][pix]
        {
            int k = kt >> 2;
            int cbase = (kt & 3) * 64;
            int c_l = t & 63, mg = t >> 6;
            const float* xc = xb + cbase + c_l;
            #pragma unroll
            for (int i = 0; i < 16; i++) {
                int m = i*4 + mg;
                const float* wt4 = swtA + (k*64 + m)*4;
                const int*   of4 = soffA + (k*64 + m)*4;
                float v = wt4[0]*xc[of4[0]] + wt4[1]*xc[of4[1]]
                        + wt4[2]*xc[of4[2]] + wt4[3]*xc[of4[3]];
                sV[c_l*PADV + m] = v;
            }
        }
        __syncthreads();
        mm_tile(sV, sW, og, pg, acc);
        __syncthreads();
    }

    // epilogue: write partials (no bias)
    float* dst = part ? g_y1b : g_y1;
    int obase = og * 4;
    #pragma unroll
    for (int pr = 0; pr < 4; pr++) {
        float2 p0 = unpack2(acc[0][pr]);
        float2 p1 = unpack2(acc[1][pr]);
        float2 p2 = unpack2(acc[2][pr]);
        float2 p3 = unpack2(acc[3][pr]);
        int pix0 = pixbase + pg*8 + pr*2;
        *(float4*)(dst + (size_t)pix0*COUT + obase)     = make_float4(p0.x, p1.x, p2.x, p3.x);
        *(float4*)(dst + (size_t)(pix0+1)*COUT + obase) = make_float4(p0.y, p1.y, p2.y, p3.y);
    }
}

// ---- 4. BN1: combine K-split partials + bias, write y1 final, partial stats ----
__global__ void k_bn1_part(const float* __restrict__ b_dcn) {
    int c = threadIdx.x;
    int base = blockIdx.x * 64;
    float bo = b_dcn[c];
    float s = 0.f, ss = 0.f;
    for (int i = 0; i < 64; i++) {
        size_t idx = (size_t)(base + i)*COUT + c;
        float v = g_y1[idx] + g_y1b[idx] + bo;
        g_y1[idx] = v;
        s += v; ss += v*v;
    }
    g_part1[blockIdx.x*2*COUT + c] = s;
    g_part1[blockIdx.x*2*COUT + COUT + c] = ss;
}

__global__ void k_bn1_fin(const float* __restrict__ gamma,
                          const float* __restrict__ beta) {
    int c = threadIdx.x;
    float s = 0.f, ss = 0.f;
    for (int j = 0; j < 256; j++) {
        s  += g_part1[j*2*COUT + c];
        ss += g_part1[j*2*COUT + COUT + c];
    }
    const float invN = 1.0f / 16384.0f;
    float mean = s * invN;
    float var = ss * invN - mean*mean;
    float rstd = rsqrtf(var + 1e-5f);
    float sc = gamma[c] * rstd;
    g_scale1[c] = sc;
    g_shift1[c] = beta[c] - mean*sc;
}

// ---- 5. transposed conv as parity-class GEMM, BN1+ReLU fused in gather ----
#define DEC_SMEM_B ((DCN_SW_F + DCN_SV_F) * 4)     // 51200 B

__global__ void k_deconv_gemm() {
    extern __shared__ float dsm2[];
    float* sW = dsm2;
    float* sV = dsm2 + DCN_SW_F;

    int t = threadIdx.x;
    int blk = blockIdx.x;              // 1024 = b*256 + oy*2 + px
    int b  = blk >> 8;
    int oy = (blk >> 1) & 127;
    int px = blk & 1;
    int py = (oy + 1) & 1;
    int oxoff = (px + 1) & 1;          // ox = 2m + oxoff

    int og = t & 31, pg = t >> 5;
    unsigned long long acc[4][4] = {{0ull,0ull,0ull,0ull},{0ull,0ull,0ull,0ull},
                                    {0ull,0ull,0ull,0ull},{0ull,0ull,0ull,0ull}};
    const float* y1b = g_y1 + (size_t)b*HH*WW*COUT;

    for (int kt = 0; kt < 8; kt++) {
        int j = kt >> 1, chalf = kt & 1;
        int jy = j >> 1, jx = j & 1;
        int ky = py + 2*jy, kx = px + 2*jx;
        int tap = ky*4 + kx;
        int ty = oy + 1 - ky;                // = 2*iy
        bool vy = (ty >= 0 && ty <= 126);
        int iy = ty >> 1;
        int ixoff = (1 - px) - jx;           // ix = m + ixoff

        // stage W tile
        #pragma unroll
        for (int i = 0; i < 8; i++) {
            int f4 = t + i*256;
            int cl = f4 >> 5, of4 = f4 & 31;
            float4 wv = *(const float4*)(g_wT2 + (size_t)tap*16384
                                         + (chalf*64 + cl)*COUT + of4*4);
            *(float4*)(sW + cl*PADW + of4*4) = wv;
        }
        // gather V tile with BN1 + ReLU
        {
            int c_l = t & 63, mg = t >> 6;
            int c = chalf*64 + c_l;
            float sc = g_scale1[c], sh = g_shift1[c];
            #pragma unroll
            for (int i = 0; i < 16; i++) {
                int m = i*4 + mg;
                int ix = m + ixoff;
                float v = 0.f;
                if (vy && ix >= 0 && ix < 64) {
                    float raw = y1b[(iy*64 + ix)*COUT + c];
                    v = fmaxf(sc*raw + sh, 0.f);
                }
                sV[c_l*PADV + m] = v;
            }
        }
        __syncthreads();
        mm_tile(sV, sW, og, pg, acc);
        __syncthreads();
    }

    // epilogue: write z (pre-BN2) NHWC
    int obase = og * 4;
    #pragma unroll
    for (int pr = 0; pr < 4; pr++) {
        float2 p0 = unpack2(acc[0][pr]);
        float2 p1 = unpack2(acc[1][pr]);
        float2 p2 = unpack2(acc[2][pr]);
        float2 p3 = unpack2(acc[3][pr]);
        int m0 = pg*8 + pr*2;
        int ox0 = 2*m0 + oxoff;
        int ox1 = ox0 + 2;
        size_t base0 = ((size_t)(b*128 + oy)*128 + ox0)*COUT + obase;
        size_t base1 = ((size_t)(b*128 + oy)*128 + ox1)*COUT + obase;
        *(float4*)(g_z + base0) = make_float4(p0.x, p1.x, p2.x, p3.x);
        *(float4*)(g_z + base1) = make_float4(p0.y, p1.y, p2.y, p3.y);
    }
}

// ---- 6. BN2 partial sums over z ----
__global__ void k_bn2_part() {
    int c = threadIdx.x;
    int base = blockIdx.x * 128;
    float s = 0.f, ss = 0.f;
    for (int i = 0; i < 128; i++) {
        float v = g_z[(size_t)(base + i)*COUT + c];
        s += v; ss += v*v;
    }
    g_part2[blockIdx.x*2*COUT + c] = s;
    g_part2[blockIdx.x*2*COUT + COUT + c] = ss;
}

__global__ void k_bn2_fin(const float* __restrict__ gamma,
                          const float* __restrict__ beta) {
    int c = threadIdx.x;
    float s = 0.f, ss = 0.f;
    for (int j = 0; j < 512; j++) {
        s  += g_part2[j*2*COUT + c];
        ss += g_part2[j*2*COUT + COUT + c];
    }
    const float invN = 1.0f / 65536.0f;
    float mean = s * invN;
    float var = ss * invN - mean*mean;
    float rstd = rsqrtf(var + 1e-5f);
    float sc = gamma[c] * rstd;
    g_scale2[c] = sc;
    g_shift2[c] = beta[c] - mean*sc;
}

// ---- 7. final: BN2 + ReLU + NHWC -> NCHW transpose into d_out ----
__global__ void k_final(float* __restrict__ out) {
    __shared__ float tile[32][33];
    int s0 = blockIdx.x * 32;
    int c0 = blockIdx.y * 32;
    int b  = blockIdx.z;
    #pragma unroll
    for (int i = 0; i < 4; i++) {
        int srow = threadIdx.y + i*8;
        int ch = c0 + threadIdx.x;
        float v = g_z[((size_t)b*16384 + s0 + srow)*COUT + ch];
        tile[srow][threadIdx.x] = fmaxf(g_scale2[ch]*v + g_shift2[ch], 0.f);
    }
    __syncthreads();
    #pragma unroll
    for (int i = 0; i < 4; i++) {
        int crow = threadIdx.y + i*8;
        out[((size_t)b*COUT + c0 + crow)*16384 + s0 + threadIdx.x] = tile[threadIdx.x][crow];
    }
}

extern "C" void kernel_launch(void* const* d_in, const int* in_sizes, int n_in,
                              void* d_out, int out_size) {
    const float* x      = (const float*)d_in[0];
    const float* w_off  = (const float*)d_in[1];
    const float* b_off  = (const float*)d_in[2];
    const float* w_dcn  = (const float*)d_in[3];
    const float* b_dcn  = (const float*)d_in[4];
    const float* gamma1 = (const float*)d_in[5];
    const float* beta1  = (const float*)d_in[6];
    const float* w_up   = (const float*)d_in[7];
    const float* gamma2 = (const float*)d_in[8];
    const float* beta2  = (const float*)d_in[9];
    float* out = (float*)d_out;

    cudaFuncSetAttribute(k_dcn_gemm,    cudaFuncAttributeMaxDynamicSharedMemorySize, DCN_SMEM_B);
    cudaFuncSetAttribute(k_deconv_gemm, cudaFuncAttributeMaxDynamicSharedMemorySize, DEC_SMEM_B);

    k_prep_w<<<(CK*COUT + 255)/256, 256>>>(w_dcn, w_off, w_up);      // idx 0
    k_transpose_x<<<(NB*HH*WW*CIN + 255)/256, 256>>>(x);             // idx 1
    k_offconv<<<NB*HH*WW/8, 256>>>(b_off);                           // idx 2
    k_dcn_gemm<<<512, 256, DCN_SMEM_B>>>();                          // idx 3 (profiled)
    k_bn1_part<<<256, COUT>>>(b_dcn);
    k_bn1_fin<<<1, COUT>>>(gamma1, beta1);
    k_deconv_gemm<<<NB*HO*2, 256, DEC_SMEM_B>>>();
    k_bn2_part<<<512, COUT>>>();
    k_bn2_fin<<<1, COUT>>>(gamma2, beta2);
    k_final<<<dim3(512, 4, NB), dim3(32, 8)>>>(out);
}